// round 12
// baseline (speedup 1.0000x reference)
#include <cuda_runtime.h>
#include <math_constants.h>

#define CCH   512
#define HH    64
#define WW    64
#define FX    7
#define FY    7
#define BINS  (FX*FY)            // 49
#define SEG   (CCH*BINS)         // 25088
#define DTOT  (SEG*6)            // 150528
#define NOUT  1024
#define KCHUNK 256
#define NCHUNKS (DTOT/KCHUNK)    // 588
#define MAXSPAN 10               // max rows/cols per adaptive bin for 64-size dim

// Scratch (no allocation allowed in kernel_launch)
__device__ float g_pools[16 * SEG];              // 16 pools, each [C, FX, FY] channel-major
__device__ float g_partial[NCHUNKS * 3 * NOUT];  // 7.2 MB
__device__ int   g_chflag[CCH];                  // per-channel done flags (zeroed by reduce for next call)

struct PoolSmem {
    float2 plane2[HH * WW / 2];       // 16 KB
    float  strip[16 * FX * WW];       // 28 KB
    int bx0[16], by0[16], bx1[16], by1[16];
    int srs[16 * FX], sre[16 * FX];
    int scs[16 * FY], sce[16 * FY];
};
struct GemmSmem {
    float sa0[KCHUNK], sa1[KCHUNK], sa2[KCHUNK];
};

// ---------------------------------------------------------------------------
// Fused kernel. bids 0..511: pool role (one channel, all 16 pools, separable
// 2-pass max, fixed-trip idempotent-clamped loops). bids 512..1099: GEMM role
// (one 256-K chunk x all 1024 N), which first spin-waits on the <=7 channel
// flags its activation slice needs, then streams W at full DRAM rate.
// Occupancy is 4 blocks/SM by construction (47KB smem, regs<=64), so all 512
// pool blocks are wave-1 resident -> no deadlock, near-full overlap.
// ---------------------------------------------------------------------------
__global__ void __launch_bounds__(256, 4) fused_kernel(
    const float* __restrict__ feature,
    const float* __restrict__ pbox,
    const float* __restrict__ obox,
    const float* __restrict__ ratio,
    const float* __restrict__ Wf)
{
    __shared__ union { PoolSmem p; GemmSmem g; } smem;
    const int bid = blockIdx.x;
    const int tid = threadIdx.x;

    if (bid < CCH) {
        // ------------------------- POOL ROLE -------------------------
        const int ch = bid;
        PoolSmem& S = smem.p;

        if (tid < 16) {
            const float rx = ratio[0], ry = ratio[1];
            int p = tid;
            int x0, y0, x1, y1;
            if (p == 0) {
                x0 = 0; y0 = 0; x1 = WW; y1 = HH;
            } else if (p < 4) {
                int i = p - 1;
                x0 = (int)rintf(pbox[i*4+0] * rx);
                y0 = (int)rintf(pbox[i*4+1] * ry);
                x1 = (int)rintf(pbox[i*4+2] * rx);
                y1 = (int)rintf(pbox[i*4+3] * ry);
            } else {
                int q = p - 4; int i = q >> 2; int j = q & 3;
                int px0 = (int)rintf(pbox[i*4+0] * rx);
                int py0 = (int)rintf(pbox[i*4+1] * ry);
                int px1 = (int)rintf(pbox[i*4+2] * rx);
                int py1 = (int)rintf(pbox[i*4+3] * ry);
                int ox0 = (int)rintf(obox[j*4+0] * rx);
                int oy0 = (int)rintf(obox[j*4+1] * ry);
                int ox1 = (int)rintf(obox[j*4+2] * rx);
                int oy1 = (int)rintf(obox[j*4+3] * ry);
                x0 = min(px0, ox0); y0 = min(py0, oy0);
                x1 = max(px1, ox1); y1 = max(py1, oy1);
            }
            S.bx0[p] = x0; S.by0[p] = y0; S.bx1[p] = x1; S.by1[p] = y1;
        }
        __syncthreads();

        // Bin-bound tables (divisions by 7 once, outside hot loops).
        if (tid < 16 * FX) {
            int p = tid / FX, i = tid - p * FX;
            int y0 = S.by0[p], h = S.by1[p] - y0;
            S.srs[tid] = y0 + (i * h) / FX;
            S.sre[tid] = y0 + ((i + 1) * h + FX - 1) / FX;
        } else if (tid >= 128 && tid < 128 + 16 * FY) {
            int t = tid - 128;
            int p = t / FY, j = t - p * FY;
            int x0 = S.bx0[p], w = S.bx1[p] - x0;
            S.scs[t] = x0 + (j * w) / FY;
            S.sce[t] = x0 + ((j + 1) * w + FY - 1) / FY;
        }

        // Coalesced plane load (1024 float4 over 256 threads = 4 each)
        {
            const float4* src = (const float4*)(feature + (size_t)ch * (HH * WW));
            float4* dst = (float4*)S.plane2;
            dst[tid]       = src[tid];
            dst[tid + 256] = src[tid + 256];
            dst[tid + 512] = src[tid + 512];
            dst[tid + 768] = src[tid + 768];
        }
        __syncthreads();

        // Pass 1: 112 strips over 8 warps = 14 serial strips/warp.
        {
            const int warp = tid >> 5;
            const int lane = tid & 31;
            #pragma unroll
            for (int s = 0; s < 14; s++) {
                const int t  = warp + s * 8;
                const int rs = S.srs[t];
                const int rl = S.sre[t] - 1;
                float2 m = make_float2(-CUDART_INF_F, -CUDART_INF_F);
                #pragma unroll
                for (int k = 0; k < MAXSPAN; k++) {
                    int r = min(rs + k, rl);    // idempotent re-max past end
                    float2 v = S.plane2[r * (WW / 2) + lane];
                    m.x = fmaxf(m.x, v.x);
                    m.y = fmaxf(m.y, v.y);
                }
                S.strip[t * WW + 2 * lane]     = m.x;
                S.strip[t * WW + 2 * lane + 1] = m.y;
            }
        }
        __syncthreads();

        // Pass 2: 784 bins over 256 threads.
        #pragma unroll
        for (int pass = 0; pass < 4; pass++) {
            int t = tid + pass * 256;
            if (t < 16 * BINS) {
                int p   = t / BINS;
                int bin = t - p * BINS;
                int i = bin / FY, j = bin - i * FY;
                int cs = S.scs[p * FY + j];
                int cl = S.sce[p * FY + j] - 1;
                const float* s = S.strip + (p * FX + i) * WW;
                float m = -CUDART_INF_F;
                #pragma unroll
                for (int k = 0; k < MAXSPAN; k++) {
                    int c = min(cs + k, cl);
                    m = fmaxf(m, s[c]);
                }
                g_pools[p * SEG + ch * BINS + bin] = m;
            }
        }

        // Publish: all writes visible, then set this channel's flag.
        __threadfence();
        __syncthreads();
        if (tid == 0) atomicExch(&g_chflag[ch], 1);

    } else {
        // ------------------------- GEMM ROLE -------------------------
        GemmSmem& S = smem.g;
        const int chunk  = bid - CCH;
        const int k0     = chunk * KCHUNK;
        const int seg    = k0 / SEG;            // 0..5
        const int within = k0 - seg * SEG;

        int p0, p1, p2;
        if (seg == 0)      { p0 = 1;       p1 = 2;       p2 = 3;       } // human[m]
        else if (seg == 5) { p0 = 0;       p1 = 0;       p2 = 0;       } // scene
        else               { p0 = 3 + seg; p1 = 7 + seg; p2 = 11 + seg; } // obj[4m+seg-1]

        // Wait for the channels covering [within, within+256)
        const int c0  = within / BINS;
        const int c1  = (within + KCHUNK - 1) / BINS;
        const int nch = c1 - c0 + 1;            // <= 7
        if (tid < nch) {
            while (atomicAdd(&g_chflag[c0 + tid], 0) == 0) { __nanosleep(200); }
        }
        __syncthreads();
        __threadfence();

        S.sa0[tid] = g_pools[p0 * SEG + within + tid];
        S.sa1[tid] = g_pools[p1 * SEG + within + tid];
        S.sa2[tid] = g_pools[p2 * SEG + within + tid];
        __syncthreads();

        const int n = tid * 4;
        const float* wp = Wf + (size_t)k0 * NOUT + n;

        float4 s0 = make_float4(0.f, 0.f, 0.f, 0.f);
        float4 s1 = s0, s2 = s0;

        for (int d = 0; d < KCHUNK; d += 8) {
            float4 w[8];
            #pragma unroll
            for (int u = 0; u < 8; u++)
                w[u] = __ldcs((const float4*)(wp + (size_t)u * NOUT));
            wp += 8 * NOUT;
            #pragma unroll
            for (int u = 0; u < 8; u++) {
                float x0 = S.sa0[d + u];
                float x1 = S.sa1[d + u];
                float x2 = S.sa2[d + u];
                s0.x = fmaf(x0, w[u].x, s0.x); s0.y = fmaf(x0, w[u].y, s0.y);
                s0.z = fmaf(x0, w[u].z, s0.z); s0.w = fmaf(x0, w[u].w, s0.w);
                s1.x = fmaf(x1, w[u].x, s1.x); s1.y = fmaf(x1, w[u].y, s1.y);
                s1.z = fmaf(x1, w[u].z, s1.z); s1.w = fmaf(x1, w[u].w, s1.w);
                s2.x = fmaf(x2, w[u].x, s2.x); s2.y = fmaf(x2, w[u].y, s2.y);
                s2.z = fmaf(x2, w[u].z, s2.z); s2.w = fmaf(x2, w[u].w, s2.w);
            }
        }

        float* outp = g_partial + (size_t)chunk * 3 * NOUT;
        *(float4*)(outp + n)            = s0;
        *(float4*)(outp + NOUT + n)     = s1;
        *(float4*)(outp + 2 * NOUT + n) = s2;
    }
}

// ---------------------------------------------------------------------------
// Deterministic reduce over the K-chunks + bias. Also re-zeroes the channel
// flags so the NEXT kernel_launch call starts clean (flags are zero-init at
// module load, so call 1 is clean too).
// ---------------------------------------------------------------------------
__global__ void __launch_bounds__(256) reduce_kernel(
    const float* __restrict__ bias, float* __restrict__ out)
{
    __shared__ float red[256];
    const int tid  = threadIdx.x;

    if (blockIdx.x == 0) {
        g_chflag[tid]       = 0;
        g_chflag[tid + 256] = 0;
    }

    const int i    = blockIdx.x * 64 + (tid & 63);   // output index 0..3071
    const int part = tid >> 6;                        // 0..3

    float s = 0.f;
    const float* src = g_partial + (size_t)(part * 147) * (3 * NOUT) + i;
    #pragma unroll 7
    for (int c = 0; c < 147; c++)
        s += src[(size_t)c * (3 * NOUT)];

    red[tid] = s;
    __syncthreads();

    if (tid < 64) {
        float t = red[tid] + red[tid + 64] + red[tid + 128] + red[tid + 192];
        out[i] = t + bias[i & (NOUT - 1)];
    }
}

extern "C" void kernel_launch(void* const* d_in, const int* in_sizes, int n_in,
                              void* d_out, int out_size)
{
    const float* feature = (const float*)d_in[0];
    const float* pbox    = (const float*)d_in[1];
    const float* obox    = (const float*)d_in[2];
    const float* ratio   = (const float*)d_in[3];
    const float* Wf      = (const float*)d_in[4];
    const float* bias    = (const float*)d_in[5];
    float* out = (float*)d_out;

    fused_kernel<<<CCH + NCHUNKS, 256>>>(feature, pbox, obox, ratio, Wf);
    reduce_kernel<<<48, 256>>>(bias, out);
}

// round 13
// speedup vs baseline: 1.0775x; 1.0775x over previous
#include <cuda_runtime.h>
#include <math_constants.h>

#define CCH   512
#define HH    64
#define WW    64
#define FX    7
#define FY    7
#define BINS  (FX*FY)            // 49
#define SEG   (CCH*BINS)         // 25088
#define DTOT  (SEG*6)            // 150528
#define NOUT  1024
#define KCHUNK 256
#define NCHUNKS (DTOT/KCHUNK)    // 588
#define MAXSPAN 10               // max rows/cols per adaptive bin for 64-size dim
#define PGRP  8                  // pools per block (2 blocks per channel)
#define RPARTS 32                // reduce: K-part slices per block
#define RCPP  19                 // ceil(588/32) chunks per part

// Scratch (no allocation allowed in kernel_launch)
__device__ float g_pools[16 * SEG];              // 16 pools, each [C, FX, FY] channel-major
__device__ float g_partial[NCHUNKS * 3 * NOUT];  // 7.2 MB

// ---------------------------------------------------------------------------
// Pool kernel: grid (512 channels, 2 pool-groups), 256 threads. Each block
// loads its channel's 64x64 plane to SMEM and computes 8 pools x 49 bins via
// separable 2-pass max. Bounds precomputed to SMEM tables; hot loops are
// fixed-trip (10) unrolled with index clamped to the bin's last valid element
// (idempotent re-max -> no predicates).
// Pool index map: 0 = scene, 1..3 = human[i], 4..15 = obj-union(i,j) (i*4+j).
// ---------------------------------------------------------------------------
__global__ void __launch_bounds__(256) pool_kernel(
    const float* __restrict__ feature,
    const float* __restrict__ pbox,   // [3,4] x1,y1,x2,y2 (image coords)
    const float* __restrict__ obox,   // [4,4]
    const float* __restrict__ ratio)  // [2]
{
    __shared__ float2 plane2[HH * WW / 2];        // 16 KB  [r][xpair]
    __shared__ float  strip[PGRP * FX * WW];      // 14 KB  [pl*FX+i][x]
    __shared__ int by0[PGRP], by1[PGRP], bxx0[PGRP], bxx1[PGRP];
    __shared__ int srs[PGRP * FX], sre[PGRP * FX];   // row-bin bounds per (pl,i)
    __shared__ int scs[PGRP * FY], sce[PGRP * FY];   // col-bin bounds per (pl,j)

    const int ch    = blockIdx.x;
    const int pbase = blockIdx.y * PGRP;
    const int tid   = threadIdx.x;

    if (tid < PGRP) {
        const float rx = ratio[0], ry = ratio[1];
        int p = pbase + tid;
        int x0, y0, x1, y1;
        if (p == 0) {
            x0 = 0; y0 = 0; x1 = WW; y1 = HH;
        } else if (p < 4) {
            int i = p - 1;
            x0 = (int)rintf(pbox[i*4+0] * rx);
            y0 = (int)rintf(pbox[i*4+1] * ry);
            x1 = (int)rintf(pbox[i*4+2] * rx);
            y1 = (int)rintf(pbox[i*4+3] * ry);
        } else {
            int q = p - 4; int i = q >> 2; int j = q & 3;
            int px0 = (int)rintf(pbox[i*4+0] * rx);
            int py0 = (int)rintf(pbox[i*4+1] * ry);
            int px1 = (int)rintf(pbox[i*4+2] * rx);
            int py1 = (int)rintf(pbox[i*4+3] * ry);
            int ox0 = (int)rintf(obox[j*4+0] * rx);
            int oy0 = (int)rintf(obox[j*4+1] * ry);
            int ox1 = (int)rintf(obox[j*4+2] * rx);
            int oy1 = (int)rintf(obox[j*4+3] * ry);
            x0 = min(px0, ox0); y0 = min(py0, oy0);
            x1 = max(px1, ox1); y1 = max(py1, oy1);
        }
        bxx0[tid] = x0; by0[tid] = y0; bxx1[tid] = x1; by1[tid] = y1;
    }
    __syncthreads();

    // Bin-bound tables (divisions by 7 happen once, outside hot loops).
    if (tid < PGRP * FX) {
        int pl = tid / FX, i = tid - pl * FX;
        int y0 = by0[pl], h = by1[pl] - y0;
        srs[tid] = y0 + (i * h) / FX;
        sre[tid] = y0 + ((i + 1) * h + FX - 1) / FX;
    } else if (tid >= 64 && tid < 64 + PGRP * FY) {
        int t = tid - 64;
        int pl = t / FY, j = t - pl * FY;
        int x0 = bxx0[pl], w = bxx1[pl] - x0;
        scs[t] = x0 + (j * w) / FY;
        sce[t] = x0 + ((j + 1) * w + FY - 1) / FY;
    }

    // Coalesced plane load (1024 float4 over 256 threads = 4 each)
    {
        const float4* src = (const float4*)(feature + (size_t)ch * (HH * WW));
        float4* dst = (float4*)plane2;
        dst[tid]       = src[tid];
        dst[tid + 256] = src[tid + 256];
        dst[tid + 512] = src[tid + 512];
        dst[tid + 768] = src[tid + 768];
    }
    __syncthreads();

    // Pass 1: 56 strips over 8 warps = 7 serial strips/warp.
    // Lane = column pair (float2), conflict-free. Unroll 10, clamped-idempotent.
    {
        const int warp = tid >> 5;
        const int lane = tid & 31;
        #pragma unroll
        for (int s = 0; s < 7; s++) {
            const int t  = warp + s * 8;
            const int rs = srs[t];
            const int rl = sre[t] - 1;          // last valid row of this bin
            float2 m = make_float2(-CUDART_INF_F, -CUDART_INF_F);
            #pragma unroll
            for (int k = 0; k < MAXSPAN; k++) {
                int r = min(rs + k, rl);        // idempotent re-max when past end
                float2 v = plane2[r * (WW / 2) + lane];
                m.x = fmaxf(m.x, v.x);
                m.y = fmaxf(m.y, v.y);
            }
            strip[t * WW + 2 * lane]     = m.x;
            strip[t * WW + 2 * lane + 1] = m.y;
        }
    }
    __syncthreads();

    // Pass 2: 392 bins over 256 threads (<=2 each). Unroll 10, clamped-idempotent.
    #pragma unroll
    for (int pass = 0; pass < 2; pass++) {
        int t = tid + pass * 256;
        if (t < PGRP * BINS) {
            int pl  = t / BINS;
            int bin = t - pl * BINS;
            int i = bin / FY, j = bin - i * FY;
            int cs = scs[pl * FY + j];
            int cl = sce[pl * FY + j] - 1;      // last valid col of this bin
            const float* s = strip + (pl * FX + i) * WW;
            float m = -CUDART_INF_F;
            #pragma unroll
            for (int k = 0; k < MAXSPAN; k++) {
                int c = min(cs + k, cl);
                m = fmaxf(m, s[c]);
            }
            g_pools[(pbase + pl) * SEG + ch * BINS + bin] = m;
        }
    }
}

// ---------------------------------------------------------------------------
// Split-K GEMM: out[m,n] = sum_d act[m,d] * W[d,n]
// act row m = concat(human[m], obj[4m..4m+3], scene); each 256-row K-chunk
// lies entirely in one concat segment (256 divides 25088), so activations
// are 3 base pointers into g_pools, staged in SMEM.
// One block = all 1024 N columns (256 thr x float4), one K-chunk of 256.
// ---------------------------------------------------------------------------
__global__ void __launch_bounds__(256, 4) gemm_kernel(const float* __restrict__ Wf)
{
    __shared__ float sa0[KCHUNK], sa1[KCHUNK], sa2[KCHUNK];

    const int chunk  = blockIdx.x;
    const int k0     = chunk * KCHUNK;
    const int seg    = k0 / SEG;            // 0..5
    const int within = k0 - seg * SEG;

    int p0, p1, p2;
    if (seg == 0)      { p0 = 1;       p1 = 2;       p2 = 3;       } // human[m]
    else if (seg == 5) { p0 = 0;       p1 = 0;       p2 = 0;       } // scene
    else               { p0 = 3 + seg; p1 = 7 + seg; p2 = 11 + seg; } // obj[4m+seg-1]

    const int tid = threadIdx.x;
    sa0[tid] = g_pools[p0 * SEG + within + tid];
    sa1[tid] = g_pools[p1 * SEG + within + tid];
    sa2[tid] = g_pools[p2 * SEG + within + tid];
    __syncthreads();

    const int n = tid * 4;
    const float* wp = Wf + (size_t)k0 * NOUT + n;

    float4 s0 = make_float4(0.f, 0.f, 0.f, 0.f);
    float4 s1 = s0, s2 = s0;

    for (int d = 0; d < KCHUNK; d += 8) {
        float4 w[8];
        #pragma unroll
        for (int u = 0; u < 8; u++)
            w[u] = __ldcs((const float4*)(wp + (size_t)u * NOUT));
        wp += 8 * NOUT;
        #pragma unroll
        for (int u = 0; u < 8; u++) {
            float x0 = sa0[d + u];
            float x1 = sa1[d + u];
            float x2 = sa2[d + u];
            s0.x = fmaf(x0, w[u].x, s0.x); s0.y = fmaf(x0, w[u].y, s0.y);
            s0.z = fmaf(x0, w[u].z, s0.z); s0.w = fmaf(x0, w[u].w, s0.w);
            s1.x = fmaf(x1, w[u].x, s1.x); s1.y = fmaf(x1, w[u].y, s1.y);
            s1.z = fmaf(x1, w[u].z, s1.z); s1.w = fmaf(x1, w[u].w, s1.w);
            s2.x = fmaf(x2, w[u].x, s2.x); s2.y = fmaf(x2, w[u].y, s2.y);
            s2.z = fmaf(x2, w[u].z, s2.z); s2.w = fmaf(x2, w[u].w, s2.w);
        }
    }

    float* outp = g_partial + (size_t)chunk * 3 * NOUT;
    *(float4*)(outp + n)            = s0;
    *(float4*)(outp + NOUT + n)     = s1;
    *(float4*)(outp + 2 * NOUT + n) = s2;
}

// ---------------------------------------------------------------------------
// Deterministic reduce + bias. 96 blocks x 1024 threads.
// Block covers 32 outputs (lane = tid&31, coalesced 128B) x 32 K-part slices
// (part = tid>>5, <=19 chunks each), then SMEM tree over parts. ~98k threads
// with deep unrolled load batches -> latency fully hidden, traffic-bound.
// ---------------------------------------------------------------------------
__global__ void __launch_bounds__(1024) reduce_kernel(
    const float* __restrict__ bias, float* __restrict__ out)
{
    __shared__ float red[RPARTS * 32];
    const int tid  = threadIdx.x;
    const int lane = tid & 31;
    const int part = tid >> 5;                       // 0..31
    const int i    = blockIdx.x * 32 + lane;         // output index 0..3071

    const int cbeg = part * RCPP;
    const int cend = min(NCHUNKS, cbeg + RCPP);

    float s = 0.f;
    const float* src = g_partial + (size_t)cbeg * (3 * NOUT) + i;
    #pragma unroll
    for (int k = 0; k < RCPP; k++) {
        if (cbeg + k < cend)
            s += src[(size_t)k * (3 * NOUT)];
    }

    red[part * 32 + lane] = s;
    __syncthreads();

    #pragma unroll
    for (int st = RPARTS / 2; st > 0; st >>= 1) {
        if (part < st)
            red[part * 32 + lane] += red[(part + st) * 32 + lane];
        __syncthreads();
    }

    if (part == 0)
        out[i] = red[lane] + bias[i & (NOUT - 1)];
}

extern "C" void kernel_launch(void* const* d_in, const int* in_sizes, int n_in,
                              void* d_out, int out_size)
{
    const float* feature = (const float*)d_in[0];
    const float* pbox    = (const float*)d_in[1];
    const float* obox    = (const float*)d_in[2];
    const float* ratio   = (const float*)d_in[3];
    const float* Wf      = (const float*)d_in[4];
    const float* bias    = (const float*)d_in[5];
    float* out = (float*)d_out;

    dim3 pgrid(CCH, 2);
    pool_kernel<<<pgrid, 256>>>(feature, pbox, obox, ratio);
    gemm_kernel<<<NCHUNKS, 256>>>(Wf);
    reduce_kernel<<<96, 1024>>>(bias, out);
}